// round 7
// baseline (speedup 1.0000x reference)
#include <cuda_runtime.h>

// Shapes: x (16,512,256) f32, target (16,512) i32, max_length 6144.
// Output = [output (16,6144,256) f32][duration_pred (16,512) f32=9.0]

#define NB   16
#define LSEQ 512
#define DDIM 256
#define ROW4 (DDIM / 4)          // 64 float4 per row
#define MLMAX 6144

// Per-output-row source index; -1 => zero row.
__device__ int g_idx[NB * MLMAX];

// 16 blocks x 512 threads: shfl scan -> interval scatter of g_idx,
// tail = -1, plus the constant-9.0 buffer.
__global__ void __launch_bounds__(LSEQ)
setup_kernel(const int* __restrict__ target,
             float* __restrict__ dur_out,
             int max_length)
{
    const int n    = blockIdx.x;
    const int tid  = threadIdx.x;
    const int wid  = tid >> 5;
    const int lane = tid & 31;

    __shared__ int warp_sums[16];

    const int d = target[n * LSEQ + tid];
    int v = d;
    #pragma unroll
    for (int off = 1; off < 32; off <<= 1) {
        int u = __shfl_up_sync(0xffffffffu, v, off);
        if (lane >= off) v += u;
    }
    if (lane == 31) warp_sums[wid] = v;
    __syncthreads();
    if (wid == 0 && lane < 16) {
        int w = warp_sums[lane];
        #pragma unroll
        for (int off = 1; off < 16; off <<= 1) {
            int u = __shfl_up_sync(0x0000ffffu, w, off);
            if (lane >= off) w += u;
        }
        warp_sums[lane] = w;
    }
    __syncthreads();

    const int cur   = v + (wid ? warp_sums[wid - 1] : 0);
    const int prev  = cur - d;
    const int total = warp_sums[15];

    int* idx = g_idx + n * max_length;

    for (int t = prev; t < cur && t < max_length; ++t)
        idx[t] = tid;

    for (int t = total + tid; t < max_length; t += LSEQ)
        idx[t] = -1;

    dur_out[n * LSEQ + tid] = 9.0f;
}

// Grid (max_length/16, NB), 256 threads. Thread group g = tid>>6 (64 threads)
// owns 4 consecutive output rows; each thread holds column d4 = tid&63.
// One int4 index load covers the 4 rows; tail rows skip the data load.
// No syncs, no smem, no division.
__global__ void __launch_bounds__(256)
gather_kernel(const float4* __restrict__ x4,
              float4*       __restrict__ out4,
              int max_length)
{
    const int n   = blockIdx.y;
    const int tid = threadIdx.x;
    const int d4  = tid & 63;
    const int r0  = blockIdx.x * 16 + (tid >> 6) * 4;   // first of 4 rows

    const int4 src = *(const int4*)(g_idx + n * max_length + r0);

    const float4* __restrict__ xb = x4 + (long)n * LSEQ * ROW4 + d4;
    float4*       __restrict__ ob = out4 + ((long)n * max_length + r0) * ROW4 + d4;

    const float4 zero = make_float4(0.f, 0.f, 0.f, 0.f);

    float4 v0 = zero, v1 = zero, v2 = zero, v3 = zero;
    if (src.x >= 0) v0 = xb[src.x * ROW4];
    if (src.y >= 0) v1 = xb[src.y * ROW4];
    if (src.z >= 0) v2 = xb[src.z * ROW4];
    if (src.w >= 0) v3 = xb[src.w * ROW4];

    ob[0 * ROW4] = v0;
    ob[1 * ROW4] = v1;
    ob[2 * ROW4] = v2;
    ob[3 * ROW4] = v3;
}

extern "C" void kernel_launch(void* const* d_in, const int* in_sizes, int n_in,
                              void* d_out, int out_size)
{
    const float* x      = (const float*)d_in[1];
    const int*   target = (const int*)  d_in[2];

    const int NL = in_sizes[2];                       // N*L = 8192
    const int max_length = (out_size - NL) / (NB * DDIM);

    float* out     = (float*)d_out;
    float* dur_out = out + (long)NB * max_length * DDIM;

    setup_kernel<<<NB, LSEQ>>>(target, dur_out, max_length);

    dim3 grid(max_length / 16, NB);                   // (384, 16)
    gather_kernel<<<grid, 256>>>((const float4*)x, (float4*)out, max_length);
}

// round 8
// speedup vs baseline: 1.0707x; 1.0707x over previous
#include <cuda_runtime.h>

// Shapes: x (16,512,256) f32, target (16,512) i32, max_length 6144.
// Output = [output (16,6144,256) f32][duration_pred (16,512) f32=9.0]

#define NB   16
#define LSEQ 512
#define DDIM 256
#define ROW4 (DDIM / 4)          // 64 float4 per row
#define MLMAX 6144
#define SETUP_SPLIT 4            // setup blocks per batch

// Per-output-row source index; -1 => zero row.
__device__ int g_idx[NB * MLMAX];

// Grid (SETUP_SPLIT, NB) x 512. Every block redundantly scans its batch's
// durations (cheap), then scatters only its 1/SETUP_SPLIT window of g_idx.
__global__ void __launch_bounds__(LSEQ)
setup_kernel(const int* __restrict__ target,
             float* __restrict__ dur_out,
             int max_length)
{
    const int n    = blockIdx.y;
    const int q    = blockIdx.x;
    const int tid  = threadIdx.x;
    const int wid  = tid >> 5;
    const int lane = tid & 31;

    __shared__ int warp_sums[16];

    const int d = target[n * LSEQ + tid];
    int v = d;
    #pragma unroll
    for (int off = 1; off < 32; off <<= 1) {
        int u = __shfl_up_sync(0xffffffffu, v, off);
        if (lane >= off) v += u;
    }
    if (lane == 31) warp_sums[wid] = v;
    __syncthreads();
    if (wid == 0 && lane < 16) {
        int w = warp_sums[lane];
        #pragma unroll
        for (int off = 1; off < 16; off <<= 1) {
            int u = __shfl_up_sync(0x0000ffffu, w, off);
            if (lane >= off) w += u;
        }
        warp_sums[lane] = w;
    }
    __syncthreads();

    const int cur   = v + (wid ? warp_sums[wid - 1] : 0);
    const int prev  = cur - d;
    const int total = warp_sums[15];

    const int win   = max_length / SETUP_SPLIT;       // 1536
    const int w0    = q * win;
    const int w1    = w0 + win;

    int* idx = g_idx + n * max_length;

    // Scatter this thread's span clipped to the window (writes only t < total).
    const int lo = prev > w0 ? prev : w0;
    const int hi = cur  < w1 ? cur  : w1;
    for (int t = lo; t < hi; ++t)
        idx[t] = tid;

    // Tail entries (t >= total) within the window; disjoint from scatter.
    for (int t = w0 + tid; t < w1; t += LSEQ)
        if (t >= total) idx[t] = -1;

    if (q == 0)
        dur_out[n * LSEQ + tid] = 9.0f;
}

// Grid (max_length/32, NB) x 256. Each 64-thread group owns 8 consecutive
// output rows at fixed column d4; two int4 idx loads; 8 independent LDG.128
// in flight; tail rows skip the load. No syncs, no smem, no division.
__global__ void __launch_bounds__(256)
gather_kernel(const float4* __restrict__ x4,
              float4*       __restrict__ out4,
              int max_length)
{
    const int n   = blockIdx.y;
    const int tid = threadIdx.x;
    const int d4  = tid & 63;
    const int r0  = blockIdx.x * 32 + (tid >> 6) * 8;   // first of 8 rows

    const int* ib = g_idx + n * max_length + r0;
    const int4 sa = *(const int4*)(ib);
    const int4 sb = *(const int4*)(ib + 4);

    const float4* __restrict__ xb = x4 + (long)n * LSEQ * ROW4 + d4;
    float4*       __restrict__ ob = out4 + ((long)n * max_length + r0) * ROW4 + d4;

    const float4 zero = make_float4(0.f, 0.f, 0.f, 0.f);

    float4 v0 = zero, v1 = zero, v2 = zero, v3 = zero;
    float4 v4 = zero, v5 = zero, v6 = zero, v7 = zero;
    if (sa.x >= 0) v0 = xb[sa.x * ROW4];
    if (sa.y >= 0) v1 = xb[sa.y * ROW4];
    if (sa.z >= 0) v2 = xb[sa.z * ROW4];
    if (sa.w >= 0) v3 = xb[sa.w * ROW4];
    if (sb.x >= 0) v4 = xb[sb.x * ROW4];
    if (sb.y >= 0) v5 = xb[sb.y * ROW4];
    if (sb.z >= 0) v6 = xb[sb.z * ROW4];
    if (sb.w >= 0) v7 = xb[sb.w * ROW4];

    ob[0 * ROW4] = v0;
    ob[1 * ROW4] = v1;
    ob[2 * ROW4] = v2;
    ob[3 * ROW4] = v3;
    ob[4 * ROW4] = v4;
    ob[5 * ROW4] = v5;
    ob[6 * ROW4] = v6;
    ob[7 * ROW4] = v7;
}

extern "C" void kernel_launch(void* const* d_in, const int* in_sizes, int n_in,
                              void* d_out, int out_size)
{
    const float* x      = (const float*)d_in[1];
    const int*   target = (const int*)  d_in[2];

    const int NL = in_sizes[2];                       // N*L = 8192
    const int max_length = (out_size - NL) / (NB * DDIM);

    float* out     = (float*)d_out;
    float* dur_out = out + (long)NB * max_length * DDIM;

    dim3 sgrid(SETUP_SPLIT, NB);                      // (4, 16)
    setup_kernel<<<sgrid, LSEQ>>>(target, dur_out, max_length);

    dim3 grid(max_length / 32, NB);                   // (192, 16)
    gather_kernel<<<grid, 256>>>((const float4*)x, (float4*)out, max_length);
}